// round 3
// baseline (speedup 1.0000x reference)
#include <cuda_runtime.h>

typedef unsigned long long ull;

#define B   8
#define NC  2
#define NS  8
#define CH  64
#define H   192
#define WI  192
#define HW  (H*WI)

// ---------------- scratch ----------------
__device__ float d_g[B*NC*HW];           // g(p) map
__device__ float d_sp[B*NC*NS*HW];       // raw space maps
__device__ float d_Z[B*NC*NS];           // per-map sums
__device__ float d_S[B*NC*NS*576];       // shifted correlations [chn*576 + i*9 + ky*3+kx]
__device__ float d_tok2[B*NC*CH];
__device__ ull   d_M2[B*32*20];          // pair (M[2op], M[2op+1]) at [b][op][k=c*9+kk], pitch 20
__device__ float d_sum[CH];
__device__ float d_ss[CH];

__device__ __forceinline__ float sigm(float x){ return 1.f/(1.f+__expf(-x)); }
__device__ __forceinline__ void ffma2(ull& d, ull a, ull b){
    asm("fma.rn.f32x2 %0, %1, %2, %0;" : "+l"(d) : "l"(a), "l"(b));
}
__device__ __forceinline__ void fadd2(ull& d, ull a){
    asm("add.rn.f32x2 %0, %0, %1;" : "+l"(d) : "l"(a));
}
__device__ __forceinline__ ull pack2(float lo, float hi){
    ull r; asm("mov.b64 %0, {%1,%2};" : "=l"(r) : "f"(lo), "f"(hi)); return r;
}
__device__ __forceinline__ float lo2(ull v){ return __uint_as_float((unsigned)v); }
__device__ __forceinline__ float hi2(ull v){ return __uint_as_float((unsigned)(v>>32)); }

// ---------------- K0: zero accumulators ----------------
__global__ void k_zero() {
    int i = blockIdx.x*256 + threadIdx.x;      // 288*256 = 73728 exact for d_S
    d_S[i] = 0.f;
    if (i < B*NC*NS)  d_Z[i] = 0.f;
    if (i < B*NC*CH)  d_tok2[i] = 0.f;
    if (i < CH) { d_sum[i] = 0.f; d_ss[i] = 0.f; }
}

// ---------------- K1: prob window from score -> space maps + Z + g (merged) ----------------
__global__ void k_pre(const float* __restrict__ score,
                      const float* __restrict__ Wk,
                      const float* __restrict__ Wcv,
                      const float* __restrict__ Wa,
                      const float* __restrict__ Wc) {
    __shared__ float wk[63];
    __shared__ float cw[8], aw[8];
    int tid = threadIdx.x;
    if (tid < 63) wk[tid] = Wk[tid];
    if (tid < 8) { cw[tid] = Wc[tid]*Wcv[tid]; aw[tid] = Wa[tid]; }
    __syncthreads();
    int bc = blockIdx.y;
    int p  = blockIdx.x*256 + tid;             // 144*256 = 36864 exact
    int h = p / WI, w = p % WI;
    const float* sc = score + bc*HW;
    float win[9];
#pragma unroll
    for (int u = 0; u < 3; u++)
#pragma unroll
        for (int v = 0; v < 3; v++) {
            int hh = h + u - 1, ww = w + v - 1;
            win[u*3+v] = (hh >= 0 && hh < H && ww >= 0 && ww < WI) ? sigm(sc[hh*WI + ww]) : 0.f;
        }
    float val[8];
    val[0] = win[4];
#pragma unroll
    for (int k = 0; k < 7; k++) {
        float a = 0.f;
#pragma unroll
        for (int j = 0; j < 9; j++) a += wk[k*9+j]*win[j];
        val[k+1] = sigm(a);
    }
#pragma unroll
    for (int k = 0; k < 8; k++) d_sp[(bc*8+k)*HW + p] = val[k];
#pragma unroll
    for (int k = 0; k < 8; k++) {
        float v = val[k];
#pragma unroll
        for (int o = 16; o > 0; o >>= 1) v += __shfl_xor_sync(0xffffffffu, v, o);
        if ((tid & 31) == 0) atomicAdd(&d_Z[bc*8+k], v);
    }
    float g = 0.f;
#pragma unroll
    for (int s = 0; s < NS; s++) g += cw[s]*sigm(aw[s]*win[4]);
    d_g[bc*HW + p] = g;
}

// ---------------- K2: S correlations, FFMA2 version ----------------
// smem: sn2 duplicated pairs [16 maps][6 rows][66 cols] pitch 397 (ull),
//       x2 channel-pairs [32 pairs][64 cols] pitch 65 (ull), invv[16].
// block 128 = 16 maps x 8 channel-groups; thread: 4 chan-pairs x 9 taps f32x2 acc.
#define KS_SN   6352
#define KS_X2   2080
#define KS_SMEM ((KS_SN + KS_X2)*8 + 64)
__global__ __launch_bounds__(128, 3) void k_S(const float* __restrict__ x,
                                              const float* __restrict__ Wcs) {
    extern __shared__ ull sm[];
    ull* sn2 = sm;
    ull* x2  = sm + KS_SN;
    float* invv = (float*)(sm + KS_SN + KS_X2);
    int rb = blockIdx.x, ct = blockIdx.y, b = blockIdx.z;
    int tid = threadIdx.x;
    int map = tid & 15, cg = tid >> 4;

    if (tid < 16) {
        int chn = (b*NC + (tid >> 3))*NS + (tid & 7);
        invv[tid] = Wcs[tid & 7] / d_Z[chn];
    }
    __syncthreads();

    for (int idx = tid; idx < 16*6*66; idx += 128) {
        int m = idx/396, rem = idx%396, r = rem/66, cc = rem%66;
        int gr = rb*4 - 1 + r, gc = ct*64 - 1 + cc;
        int chn = (b*NC + (m >> 3))*NS + (m & 7);
        float v = 0.f;
        if (gr >= 0 && gr < H && gc >= 0 && gc < WI)
            v = d_sp[chn*HW + gr*WI + gc] * invv[m];
        sn2[m*397 + r*66 + cc] = pack2(v, v);
    }

    ull acc[4][9];
#pragma unroll
    for (int p = 0; p < 4; p++)
#pragma unroll
        for (int k = 0; k < 9; k++) acc[p][k] = 0ull;

    for (int r = 0; r < 4; r++) {
        __syncthreads();
        int hh = rb*4 + r;
        for (int idx = tid; idx < 32*64; idx += 128) {
            int pr = idx >> 6, col = idx & 63;
            const float* xb = &x[((b*CH + 2*pr)*H + hh)*WI + ct*64 + col];
            x2[pr*65 + col] = pack2(xb[0], xb[HW]);
        }
        __syncthreads();
        const ull* snp = &sn2[map*397 + r*66];
        const ull* xp  = &x2[cg*4*65];
#pragma unroll 2
        for (int j = 0; j < 64; j++) {
            ull w0 = snp[j],       w1 = snp[j+1],       w2 = snp[j+2];
            ull w3 = snp[66+j],    w4 = snp[66+j+1],    w5 = snp[66+j+2];
            ull w6 = snp[132+j],   w7 = snp[132+j+1],   w8 = snp[132+j+2];
#pragma unroll
            for (int p = 0; p < 4; p++) {
                ull xv = xp[p*65 + j];
                ffma2(acc[p][0], xv, w0); ffma2(acc[p][1], xv, w1); ffma2(acc[p][2], xv, w2);
                ffma2(acc[p][3], xv, w3); ffma2(acc[p][4], xv, w4); ffma2(acc[p][5], xv, w5);
                ffma2(acc[p][6], xv, w6); ffma2(acc[p][7], xv, w7); ffma2(acc[p][8], xv, w8);
            }
        }
    }
    int chn = (b*NC + (map >> 3))*NS + (map & 7);
    float* Sb = &d_S[chn*576];
#pragma unroll
    for (int p = 0; p < 4; p++) {
        int i0 = cg*8 + 2*p;
#pragma unroll
        for (int ky = 0; ky < 3; ky++)
#pragma unroll
            for (int kx = 0; kx < 3; kx++) {
                ull a = acc[p][(2-ky)*3 + (2-kx)];
                atomicAdd(&Sb[i0*9 + ky*3 + kx],     lo2(a));
                atomicAdd(&Sb[(i0+1)*9 + ky*3 + kx], hi2(a));
            }
    }
}

// ---------------- K3: tok2[b,c,d] = sum_{s,i,tau} Wx[(s*64+d),i,tau] * S[b,c,s,i,tau] ----------------
__global__ void k_tok(const float* __restrict__ Wx) {
    __shared__ alignas(16) float Ss[576];
    int bcs = blockIdx.x;                      // 128 blocks
    int tid = threadIdx.x;                     // 64 = d
    for (int i = tid; i < 576; i += 64) Ss[i] = d_S[bcs*576 + i];
    __syncthreads();
    int s = bcs & 7;
    const ulonglong2* wr = (const ulonglong2*)(Wx + (s*64 + tid)*576);
    const ulonglong2* sr = (const ulonglong2*)Ss;
    ull a0 = 0ull, a1 = 0ull;
#pragma unroll 4
    for (int j = 0; j < 144; j++) {
        ulonglong2 wv = wr[j], sv = sr[j];
        ffma2(a0, wv.x, sv.x);
        ffma2(a1, wv.y, sv.y);
    }
    float acc = (lo2(a0) + hi2(a0)) + (lo2(a1) + hi2(a1));
    atomicAdd(&d_tok2[(bcs >> 3)*64 + tid], acc);
}

// ---------------- K4: M2[b][op][k] = pair over output channels ----------------
__global__ void k_M(const float* __restrict__ Ws) {
    __shared__ float t2[128];
    int b = blockIdx.x, tid = threadIdx.x;     // 128
    t2[tid] = d_tok2[b*128 + tid];
    __syncthreads();
    for (int idx = tid; idx < 32*18; idx += 128) {
        int op = idx/18, k = idx%18, c = k/9, kk = k%9;
        const float* tp = t2 + c*64;
        const float* w0 = Ws + (2*op)*576 + kk;
        const float* w1 = Ws + (2*op+1)*576 + kk;
        float a0 = 0.f, a1 = 0.f;
#pragma unroll 8
        for (int i = 0; i < 64; i++) { a0 += w0[i*9]*tp[i]; a1 += w1[i*9]*tp[i]; }
        d_M2[(b*32 + op)*20 + k] = pack2(a0, a1);
    }
}

// ---------------- K5: BN stats of recomputed y0, FFMA2 channel-pairs ----------------
__global__ __launch_bounds__(256) void k_stats() {
    __shared__ alignas(16) ull g2[2*10*200];   // duplicated (v,v), 32KB
    __shared__ float4 redv[256];
    int band = blockIdx.x, b = blockIdx.y;
    int tid = threadIdx.x;
    int op = tid & 31, cg = tid >> 5;

    for (int idx = tid; idx < 2*10*194; idx += 256) {
        int c = idx/1940, rem = idx%1940, r = rem/194, cc = rem%194;
        int gr = band*8 - 1 + r, gc = cc - 1;
        float v = 0.f;
        if (gr >= 0 && gr < H && gc >= 0 && gc < WI) v = d_g[(b*2 + c)*HW + gr*WI + gc];
        g2[c*2000 + r*200 + cc] = pack2(v, v);
    }
    ull m2[18];
#pragma unroll
    for (int k = 0; k < 18; k++) m2[k] = d_M2[(b*32 + op)*20 + k];
    __syncthreads();

    ull s2 = 0ull, q2 = 0ull;
    for (int r = 0; r < 8; r++) {
#pragma unroll
        for (int jt = 0; jt < 6; jt++) {
            int j = cg*24 + jt*4;
            ull wd[2][3][6];
#pragma unroll
            for (int c = 0; c < 2; c++)
#pragma unroll
                for (int u = 0; u < 3; u++) {
                    const ulonglong2* gp = (const ulonglong2*)&g2[c*2000 + (r+u)*200 + j];
                    ulonglong2 A = gp[0], Bv = gp[1], Cv = gp[2];
                    wd[c][u][0]=A.x;  wd[c][u][1]=A.y;
                    wd[c][u][2]=Bv.x; wd[c][u][3]=Bv.y;
                    wd[c][u][4]=Cv.x; wd[c][u][5]=Cv.y;
                }
#pragma unroll
            for (int q = 0; q < 4; q++) {
                ull y = 0ull;
#pragma unroll
                for (int c = 0; c < 2; c++)
#pragma unroll
                    for (int ky = 0; ky < 3; ky++)
#pragma unroll
                        for (int kx = 0; kx < 3; kx++)
                            ffma2(y, m2[c*9 + ky*3 + kx], wd[c][ky][q+kx]);
                fadd2(s2, y);
                ffma2(q2, y, y);
            }
        }
    }
    redv[tid] = make_float4(lo2(s2), hi2(s2), lo2(q2), hi2(q2));
    __syncthreads();
    if (tid < 32) {
        float4 a = redv[tid];
#pragma unroll
        for (int g = 1; g < 8; g++) {
            float4 t = redv[tid + 32*g];
            a.x += t.x; a.y += t.y; a.z += t.z; a.w += t.w;
        }
        atomicAdd(&d_sum[2*tid],   a.x);
        atomicAdd(&d_sum[2*tid+1], a.y);
        atomicAdd(&d_ss[2*tid],    a.z);
        atomicAdd(&d_ss[2*tid+1],  a.w);
    }
}

// ---------------- K6: out = x + relu(y0*scale + shift), FFMA2, BN finalize folded in ----------------
__global__ __launch_bounds__(256) void k_out(const float* __restrict__ x,
                                             float* __restrict__ out,
                                             const float* __restrict__ gamma,
                                             const float* __restrict__ beta) {
    __shared__ alignas(16) ull g2[2*10*200];
    __shared__ ull M2s[32*20];
    __shared__ float sc[64], sh[64];
    int band = blockIdx.x, b = blockIdx.y;
    int tid = threadIdx.x;

    for (int idx = tid; idx < 2*10*194; idx += 256) {
        int c = idx/1940, rem = idx%1940, r = rem/194, cc = rem%194;
        int gr = band*8 - 1 + r, gc = cc - 1;
        float v = 0.f;
        if (gr >= 0 && gr < H && gc >= 0 && gc < WI) v = d_g[(b*2 + c)*HW + gr*WI + gc];
        g2[c*2000 + r*200 + cc] = pack2(v, v);
    }
    for (int idx = tid; idx < 640; idx += 256) M2s[idx] = d_M2[b*640 + idx];
    if (tid < 64) {
        float n = (float)(B*HW);
        float mean = d_sum[tid]/n;
        float var  = d_ss[tid]/n - mean*mean;
        float s = gamma[tid]*rsqrtf(var + 1e-5f);
        sc[tid] = s;
        sh[tid] = beta[tid] - mean*s;
    }
    __syncthreads();

    for (int p = tid; p < 8*192; p += 256) {
        int r = p/192, w = p%192;
        int hh = band*8 + r;
        ull win2[18];
#pragma unroll
        for (int c = 0; c < 2; c++)
#pragma unroll
            for (int ky = 0; ky < 3; ky++)
#pragma unroll
                for (int kx = 0; kx < 3; kx++)
                    win2[c*9 + ky*3 + kx] = g2[c*2000 + (r+ky)*200 + (w+kx)];
        int base = (b*CH)*HW + hh*WI + w;
#pragma unroll 2
        for (int op = 0; op < 32; op++) {
            ull acc = 0ull;
#pragma unroll
            for (int k = 0; k < 18; k++) ffma2(acc, M2s[op*20 + k], win2[k]);
            int o0 = 2*op;
            float v0 = fmaxf(lo2(acc)*sc[o0]   + sh[o0],   0.f);
            float v1 = fmaxf(hi2(acc)*sc[o0+1] + sh[o0+1], 0.f);
            int g0 = base + o0*HW;
            out[g0]      = x[g0]      + v0;
            out[g0+HW]   = x[g0+HW]   + v1;
        }
    }
}

// ---------------- launch ----------------
extern "C" void kernel_launch(void* const* d_in, const int* in_sizes, int n_in,
                              void* d_out, int out_size) {
    const float* x     = (const float*)d_in[0];
    const float* score = (const float*)d_in[1];
    const float* Wk    = (const float*)d_in[2];   // W_cspace (7,1,3,3)
    const float* Wx    = (const float*)d_in[3];   // W_xspace (512,64,3,3)
    const float* Wcs   = (const float*)d_in[4];   // W_combine_space (8)
    const float* Wcv   = (const float*)d_in[5];   // W_cvalue (8)
    const float* Wa    = (const float*)d_in[6];   // W_attn (8)
    const float* Wc    = (const float*)d_in[7];   // W_combine (8)
    const float* Ws    = (const float*)d_in[8];   // W_single (64,64,3,3)
    const float* gamma = (const float*)d_in[9];
    const float* beta  = (const float*)d_in[10];
    float* out = (float*)d_out;

    cudaFuncSetAttribute(k_S, cudaFuncAttributeMaxDynamicSharedMemorySize, KS_SMEM);

    k_zero<<<288, 256>>>();
    { dim3 g(144, 16); k_pre<<<g, 256>>>(score, Wk, Wcv, Wa, Wc); }
    { dim3 g(48, 3, 8); k_S<<<g, 128, KS_SMEM>>>(x, Wcs); }
    k_tok<<<128, 64>>>(Wx);
    k_M<<<8, 128>>>(Ws);
    { dim3 g(24, 8); k_stats<<<g, 256>>>(); }
    { dim3 g(24, 8); k_out<<<g, 256>>>(x, out, gamma, beta);
    }
}

// round 4
// speedup vs baseline: 1.0288x; 1.0288x over previous
#include <cuda_runtime.h>

typedef unsigned long long ull;

#define B   8
#define NC  2
#define NS  8
#define CH  64
#define H   192
#define WI  192
#define HW  (H*WI)

// ---------------- scratch ----------------
__device__ float d_g[B*NC*HW];           // g(p) map
__device__ float d_sp[B*NC*NS*HW];       // raw space maps
__device__ float d_Z[B*NC*NS];           // per-map sums
__device__ float d_S[B*NC*NS*576];       // shifted correlations [chn*576 + i*9 + ky*3+kx]
__device__ float d_tok2[B*NC*CH];
__device__ ull   d_M2[B*32*20];          // pair (M[2op], M[2op+1]) at [b][op][k=c*9+kk], pitch 20
__device__ float d_sum[CH];
__device__ float d_ss[CH];

__device__ __forceinline__ float sigm(float x){ return 1.f/(1.f+__expf(-x)); }
__device__ __forceinline__ void ffma2(ull& d, ull a, ull b){
    asm("fma.rn.f32x2 %0, %1, %2, %0;" : "+l"(d) : "l"(a), "l"(b));
}
__device__ __forceinline__ void fadd2(ull& d, ull a){
    asm("add.rn.f32x2 %0, %0, %1;" : "+l"(d) : "l"(a));
}
__device__ __forceinline__ ull pack2(float lo, float hi){
    ull r; asm("mov.b64 %0, {%1,%2};" : "=l"(r) : "f"(lo), "f"(hi)); return r;
}
__device__ __forceinline__ float lo2(ull v){ return __uint_as_float((unsigned)v); }
__device__ __forceinline__ float hi2(ull v){ return __uint_as_float((unsigned)(v>>32)); }

// ---------------- K0: zero accumulators ----------------
__global__ void k_zero() {
    int i = blockIdx.x*256 + threadIdx.x;      // 288*256 = 73728 exact for d_S
    d_S[i] = 0.f;
    if (i < B*NC*NS)  d_Z[i] = 0.f;
    if (i < B*NC*CH)  d_tok2[i] = 0.f;
    if (i < CH) { d_sum[i] = 0.f; d_ss[i] = 0.f; }
}

// ---------------- K1: prob window from score -> space maps + Z + g (merged) ----------------
__global__ void k_pre(const float* __restrict__ score,
                      const float* __restrict__ Wk,
                      const float* __restrict__ Wcv,
                      const float* __restrict__ Wa,
                      const float* __restrict__ Wc) {
    __shared__ float wk[63];
    __shared__ float cw[8], aw[8];
    int tid = threadIdx.x;
    if (tid < 63) wk[tid] = Wk[tid];
    if (tid < 8) { cw[tid] = Wc[tid]*Wcv[tid]; aw[tid] = Wa[tid]; }
    __syncthreads();
    int bc = blockIdx.y;
    int p  = blockIdx.x*256 + tid;             // 144*256 = 36864 exact
    int h = p / WI, w = p % WI;
    const float* sc = score + bc*HW;
    float win[9];
#pragma unroll
    for (int u = 0; u < 3; u++)
#pragma unroll
        for (int v = 0; v < 3; v++) {
            int hh = h + u - 1, ww = w + v - 1;
            win[u*3+v] = (hh >= 0 && hh < H && ww >= 0 && ww < WI) ? sigm(sc[hh*WI + ww]) : 0.f;
        }
    float val[8];
    val[0] = win[4];
#pragma unroll
    for (int k = 0; k < 7; k++) {
        float a = 0.f;
#pragma unroll
        for (int j = 0; j < 9; j++) a += wk[k*9+j]*win[j];
        val[k+1] = sigm(a);
    }
#pragma unroll
    for (int k = 0; k < 8; k++) d_sp[(bc*8+k)*HW + p] = val[k];
#pragma unroll
    for (int k = 0; k < 8; k++) {
        float v = val[k];
#pragma unroll
        for (int o = 16; o > 0; o >>= 1) v += __shfl_xor_sync(0xffffffffu, v, o);
        if ((tid & 31) == 0) atomicAdd(&d_Z[bc*8+k], v);
    }
    float g = 0.f;
#pragma unroll
    for (int s = 0; s < NS; s++) g += cw[s]*sigm(aw[s]*win[4]);
    d_g[bc*HW + p] = g;
}

// ---------------- K2: S correlations, FFMA2 version ----------------
// smem: sn2 duplicated pairs [16 maps][6 rows][66 cols] pitch 397 (ull),
//       x2 channel-pairs [32 pairs][64 cols] pitch 65 (ull), invv[16].
// block 128 = 16 maps x 8 channel-groups; thread: 4 chan-pairs x 9 taps f32x2 acc.
#define KS_SN   6352
#define KS_X2   2080
#define KS_SMEM ((KS_SN + KS_X2)*8 + 64)
__global__ __launch_bounds__(128, 3) void k_S(const float* __restrict__ x,
                                              const float* __restrict__ Wcs) {
    extern __shared__ ull sm[];
    ull* sn2 = sm;
    ull* x2  = sm + KS_SN;
    float* invv = (float*)(sm + KS_SN + KS_X2);
    int rb = blockIdx.x, ct = blockIdx.y, b = blockIdx.z;
    int tid = threadIdx.x;
    int map = tid & 15, cg = tid >> 4;

    if (tid < 16) {
        int chn = (b*NC + (tid >> 3))*NS + (tid & 7);
        invv[tid] = Wcs[tid & 7] / d_Z[chn];
    }
    __syncthreads();

    for (int idx = tid; idx < 16*6*66; idx += 128) {
        int m = idx/396, rem = idx%396, r = rem/66, cc = rem%66;
        int gr = rb*4 - 1 + r, gc = ct*64 - 1 + cc;
        int chn = (b*NC + (m >> 3))*NS + (m & 7);
        float v = 0.f;
        if (gr >= 0 && gr < H && gc >= 0 && gc < WI)
            v = d_sp[chn*HW + gr*WI + gc] * invv[m];
        sn2[m*397 + r*66 + cc] = pack2(v, v);
    }

    ull acc[4][9];
#pragma unroll
    for (int p = 0; p < 4; p++)
#pragma unroll
        for (int k = 0; k < 9; k++) acc[p][k] = 0ull;

    for (int r = 0; r < 4; r++) {
        __syncthreads();
        int hh = rb*4 + r;
        for (int idx = tid; idx < 32*64; idx += 128) {
            int pr = idx >> 6, col = idx & 63;
            const float* xb = &x[((b*CH + 2*pr)*H + hh)*WI + ct*64 + col];
            x2[pr*65 + col] = pack2(xb[0], xb[HW]);
        }
        __syncthreads();
        const ull* snp = &sn2[map*397 + r*66];
        const ull* xp  = &x2[cg*4*65];
#pragma unroll 2
        for (int j = 0; j < 64; j++) {
            ull w0 = snp[j],       w1 = snp[j+1],       w2 = snp[j+2];
            ull w3 = snp[66+j],    w4 = snp[66+j+1],    w5 = snp[66+j+2];
            ull w6 = snp[132+j],   w7 = snp[132+j+1],   w8 = snp[132+j+2];
#pragma unroll
            for (int p = 0; p < 4; p++) {
                ull xv = xp[p*65 + j];
                ffma2(acc[p][0], xv, w0); ffma2(acc[p][1], xv, w1); ffma2(acc[p][2], xv, w2);
                ffma2(acc[p][3], xv, w3); ffma2(acc[p][4], xv, w4); ffma2(acc[p][5], xv, w5);
                ffma2(acc[p][6], xv, w6); ffma2(acc[p][7], xv, w7); ffma2(acc[p][8], xv, w8);
            }
        }
    }
    int chn = (b*NC + (map >> 3))*NS + (map & 7);
    float* Sb = &d_S[chn*576];
#pragma unroll
    for (int p = 0; p < 4; p++) {
        int i0 = cg*8 + 2*p;
#pragma unroll
        for (int ky = 0; ky < 3; ky++)
#pragma unroll
            for (int kx = 0; kx < 3; kx++) {
                ull a = acc[p][(2-ky)*3 + (2-kx)];
                atomicAdd(&Sb[i0*9 + ky*3 + kx],     lo2(a));
                atomicAdd(&Sb[(i0+1)*9 + ky*3 + kx], hi2(a));
            }
    }
}

// ---------------- K3: tok2[b,c,d] = sum_{s,i,tau} Wx[(s*64+d),i,tau] * S[b,c,s,i,tau] ----------------
__global__ void k_tok(const float* __restrict__ Wx) {
    __shared__ alignas(16) float Ss[576];
    int bcs = blockIdx.x;                      // 128 blocks
    int tid = threadIdx.x;                     // 64 = d
    for (int i = tid; i < 576; i += 64) Ss[i] = d_S[bcs*576 + i];
    __syncthreads();
    int s = bcs & 7;
    const ulonglong2* wr = (const ulonglong2*)(Wx + (s*64 + tid)*576);
    const ulonglong2* sr = (const ulonglong2*)Ss;
    ull a0 = 0ull, a1 = 0ull;
#pragma unroll 4
    for (int j = 0; j < 144; j++) {
        ulonglong2 wv = wr[j], sv = sr[j];
        ffma2(a0, wv.x, sv.x);
        ffma2(a1, wv.y, sv.y);
    }
    float acc = (lo2(a0) + hi2(a0)) + (lo2(a1) + hi2(a1));
    atomicAdd(&d_tok2[(bcs >> 3)*64 + tid], acc);
}

// ---------------- K4: M2[b][op][k] = pair over output channels ----------------
__global__ void k_M(const float* __restrict__ Ws) {
    __shared__ float t2[128];
    int b = blockIdx.x, tid = threadIdx.x;     // 128
    t2[tid] = d_tok2[b*128 + tid];
    __syncthreads();
    for (int idx = tid; idx < 32*18; idx += 128) {
        int op = idx/18, k = idx%18, c = k/9, kk = k%9;
        const float* tp = t2 + c*64;
        const float* w0 = Ws + (2*op)*576 + kk;
        const float* w1 = Ws + (2*op+1)*576 + kk;
        float a0 = 0.f, a1 = 0.f;
#pragma unroll 8
        for (int i = 0; i < 64; i++) { a0 += w0[i*9]*tp[i]; a1 += w1[i*9]*tp[i]; }
        d_M2[(b*32 + op)*20 + k] = pack2(a0, a1);
    }
}

// ---------------- K5: BN stats of recomputed y0, FFMA2 channel-pairs ----------------
__global__ __launch_bounds__(256) void k_stats() {
    __shared__ alignas(16) ull g2[2*10*200];   // duplicated (v,v), 32KB
    __shared__ float4 redv[256];
    int band = blockIdx.x, b = blockIdx.y;
    int tid = threadIdx.x;
    int op = tid & 31, cg = tid >> 5;

    for (int idx = tid; idx < 2*10*194; idx += 256) {
        int c = idx/1940, rem = idx%1940, r = rem/194, cc = rem%194;
        int gr = band*8 - 1 + r, gc = cc - 1;
        float v = 0.f;
        if (gr >= 0 && gr < H && gc >= 0 && gc < WI) v = d_g[(b*2 + c)*HW + gr*WI + gc];
        g2[c*2000 + r*200 + cc] = pack2(v, v);
    }
    ull m2[18];
#pragma unroll
    for (int k = 0; k < 18; k++) m2[k] = d_M2[(b*32 + op)*20 + k];
    __syncthreads();

    ull s2 = 0ull, q2 = 0ull;
    for (int r = 0; r < 8; r++) {
#pragma unroll
        for (int jt = 0; jt < 6; jt++) {
            int j = cg*24 + jt*4;
            ull wd[2][3][6];
#pragma unroll
            for (int c = 0; c < 2; c++)
#pragma unroll
                for (int u = 0; u < 3; u++) {
                    const ulonglong2* gp = (const ulonglong2*)&g2[c*2000 + (r+u)*200 + j];
                    ulonglong2 A = gp[0], Bv = gp[1], Cv = gp[2];
                    wd[c][u][0]=A.x;  wd[c][u][1]=A.y;
                    wd[c][u][2]=Bv.x; wd[c][u][3]=Bv.y;
                    wd[c][u][4]=Cv.x; wd[c][u][5]=Cv.y;
                }
#pragma unroll
            for (int q = 0; q < 4; q++) {
                ull y = 0ull;
#pragma unroll
                for (int c = 0; c < 2; c++)
#pragma unroll
                    for (int ky = 0; ky < 3; ky++)
#pragma unroll
                        for (int kx = 0; kx < 3; kx++)
                            ffma2(y, m2[c*9 + ky*3 + kx], wd[c][ky][q+kx]);
                fadd2(s2, y);
                ffma2(q2, y, y);
            }
        }
    }
    redv[tid] = make_float4(lo2(s2), hi2(s2), lo2(q2), hi2(q2));
    __syncthreads();
    if (tid < 32) {
        float4 a = redv[tid];
#pragma unroll
        for (int g = 1; g < 8; g++) {
            float4 t = redv[tid + 32*g];
            a.x += t.x; a.y += t.y; a.z += t.z; a.w += t.w;
        }
        atomicAdd(&d_sum[2*tid],   a.x);
        atomicAdd(&d_sum[2*tid+1], a.y);
        atomicAdd(&d_ss[2*tid],    a.z);
        atomicAdd(&d_ss[2*tid+1],  a.w);
    }
}

// ---------------- K6: out = x + relu(y0*scale + shift), FFMA2, BN finalize folded in ----------------
__global__ __launch_bounds__(256) void k_out(const float* __restrict__ x,
                                             float* __restrict__ out,
                                             const float* __restrict__ gamma,
                                             const float* __restrict__ beta) {
    __shared__ alignas(16) ull g2[2*10*200];
    __shared__ ull M2s[32*20];
    __shared__ float sc[64], sh[64];
    int band = blockIdx.x, b = blockIdx.y;
    int tid = threadIdx.x;

    for (int idx = tid; idx < 2*10*194; idx += 256) {
        int c = idx/1940, rem = idx%1940, r = rem/194, cc = rem%194;
        int gr = band*8 - 1 + r, gc = cc - 1;
        float v = 0.f;
        if (gr >= 0 && gr < H && gc >= 0 && gc < WI) v = d_g[(b*2 + c)*HW + gr*WI + gc];
        g2[c*2000 + r*200 + cc] = pack2(v, v);
    }
    for (int idx = tid; idx < 640; idx += 256) M2s[idx] = d_M2[b*640 + idx];
    if (tid < 64) {
        float n = (float)(B*HW);
        float mean = d_sum[tid]/n;
        float var  = d_ss[tid]/n - mean*mean;
        float s = gamma[tid]*rsqrtf(var + 1e-5f);
        sc[tid] = s;
        sh[tid] = beta[tid] - mean*s;
    }
    __syncthreads();

    for (int p = tid; p < 8*192; p += 256) {
        int r = p/192, w = p%192;
        int hh = band*8 + r;
        ull win2[18];
#pragma unroll
        for (int c = 0; c < 2; c++)
#pragma unroll
            for (int ky = 0; ky < 3; ky++)
#pragma unroll
                for (int kx = 0; kx < 3; kx++)
                    win2[c*9 + ky*3 + kx] = g2[c*2000 + (r+ky)*200 + (w+kx)];
        int base = (b*CH)*HW + hh*WI + w;
#pragma unroll 2
        for (int op = 0; op < 32; op++) {
            ull acc = 0ull;
#pragma unroll
            for (int k = 0; k < 18; k++) ffma2(acc, M2s[op*20 + k], win2[k]);
            int o0 = 2*op;
            float v0 = fmaxf(lo2(acc)*sc[o0]   + sh[o0],   0.f);
            float v1 = fmaxf(hi2(acc)*sc[o0+1] + sh[o0+1], 0.f);
            int g0 = base + o0*HW;
            out[g0]      = x[g0]      + v0;
            out[g0+HW]   = x[g0+HW]   + v1;
        }
    }
}

// ---------------- launch ----------------
extern "C" void kernel_launch(void* const* d_in, const int* in_sizes, int n_in,
                              void* d_out, int out_size) {
    const float* x     = (const float*)d_in[0];
    const float* score = (const float*)d_in[1];
    const float* Wk    = (const float*)d_in[2];   // W_cspace (7,1,3,3)
    const float* Wx    = (const float*)d_in[3];   // W_xspace (512,64,3,3)
    const float* Wcs   = (const float*)d_in[4];   // W_combine_space (8)
    const float* Wcv   = (const float*)d_in[5];   // W_cvalue (8)
    const float* Wa    = (const float*)d_in[6];   // W_attn (8)
    const float* Wc    = (const float*)d_in[7];   // W_combine (8)
    const float* Ws    = (const float*)d_in[8];   // W_single (64,64,3,3)
    const float* gamma = (const float*)d_in[9];
    const float* beta  = (const float*)d_in[10];
    float* out = (float*)d_out;

    cudaFuncSetAttribute(k_S, cudaFuncAttributeMaxDynamicSharedMemorySize, KS_SMEM);

    k_zero<<<288, 256>>>();
    { dim3 g(144, 16); k_pre<<<g, 256>>>(score, Wk, Wcv, Wa, Wc); }
    { dim3 g(48, 3, 8); k_S<<<g, 128, KS_SMEM>>>(x, Wcs); }
    k_tok<<<128, 64>>>(Wx);
    k_M<<<8, 128>>>(Ws);
    { dim3 g(24, 8); k_stats<<<g, 256>>>(); }
    { dim3 g(24, 8); k_out<<<g, 256>>>(x, out, gamma, beta);
    }
}